// round 8
// baseline (speedup 1.0000x reference)
#include <cuda_runtime.h>
#include <cstdint>

// ============================ problem constants ============================
constexpr int IMGC = 224;
constexpr int KTOT = IMGC * IMGC;     // 50176
constexpr int BQ   = 256;
constexpr int JN   = 25;
constexpr int TN   = 64;
constexpr int OUTN = 256;
constexpr int MIDJ = JN / 2;          // 12
constexpr int BOXC = 20;

constexpr int XG    = 28;             // x groups (grid.x)
constexpr int XPG   = 8;              // x per group: 28*8 = 224
constexpr int NQ    = 4;              // n quarters (grid.y), 64 n each
constexpr int NCOL  = 64;             // n columns per CTA
constexpr int PITCH = 225;            // 225 % 32 == 1 -> conflict-free

// smem: S[64][225] floats + accS[256][64] floats + totals[256]
constexpr uint32_t OFF_S   = 0;                          // 57600 B
constexpr uint32_t OFF_ACC = NCOL * PITCH * 4;           // 57600
constexpr uint32_t OFF_TOT = OFF_ACC + BQ * NCOL * 4;    // 123136
constexpr uint32_t SMEM_MAIN = OFF_TOT + 256 * 4;        // 124160 B

// ============================ scratch (device globals) =====================
__device__ __align__(256) unsigned long long g_bits[(size_t)IMGC * BQ * 4]; // 1.8MB
__device__ __align__(256) float g_part[(size_t)XG * BQ * OUTN];             // 7.3MB
__device__ int g_px[BQ * JN];
__device__ int g_ylo[BQ * JN];
__device__ int g_yhi[BQ * JN];

// ============================ kernel 1: farthest-frame box params ==========
__global__ void prep_kernel(const float* __restrict__ sk) {
    int id = blockIdx.x * blockDim.x + threadIdx.x;
    if (id >= BQ * JN) return;
    int b = id / JN, j = id % JN;
    const float* base = sk + ((size_t)b * JN + j) * TN * 3;
    const float* midb = sk + ((size_t)b * JN + MIDJ) * TN * 3;

    float best = -1.0f;
    int   tb = 0;
    for (int t = 0; t < TN; t++) {
        float dx = base[t * 3 + 0] - midb[t * 3 + 0];
        float dy = base[t * 3 + 1] - midb[t * 3 + 1];
        float dz = base[t * 3 + 2] - midb[t * 3 + 2];
        float d2 = __fadd_rn(__fadd_rn(__fmul_rn(dx, dx), __fmul_rn(dy, dy)),
                             __fmul_rn(dz, dz));
        float d = __fsqrt_rn(d2);
        if (d > best) { best = d; tb = t; }   // first-max == argmax semantics
    }
    float x = base[tb * 3 + 0];
    float y = base[tb * 3 + 1];
    int px = (int)(__fmul_rn(x, 224.0f));     // truncation == astype(int32)
    int py = (int)(__fmul_rn(y, 224.0f));
    g_px[id]  = px;
    g_ylo[id] = (py < BOXC) ? 0 : py - BOXC;
    g_yhi[id] = (py > IMGC - BOXC) ? IMGC : py + BOXC;
}

// ============================ kernel 2: per-(b,x) y-bitmask =================
__global__ void bitmask_kernel() {
    const int x = blockIdx.x;
    const int b = threadIdx.x;

    unsigned long long m[4] = {0ull, 0ull, 0ull, 0ull};
#pragma unroll
    for (int j = 0; j < JN; j++) {
        if (j == MIDJ) continue;
        int px = g_px[b * JN + j];
        if (x >= px - BOXC && x < px + BOXC) {
            int lo = g_ylo[b * JN + j];
            int hi = g_yhi[b * JN + j];
#pragma unroll
            for (int w = 0; w < 4; w++) {
                int l = lo - w * 64;  if (l < 0)  l = 0;
                int h = hi - w * 64;  if (h > 64) h = 64;
                if (l < h) {
                    unsigned long long hiM = (h == 64) ? ~0ull : ((1ull << h) - 1ull);
                    unsigned long long loM = (1ull << l) - 1ull;
                    m[w] |= hiM & ~loM;
                }
            }
        }
    }
    unsigned long long* dst = g_bits + ((size_t)x * BQ + b) * 4;
    dst[0] = m[0]; dst[1] = m[1]; dst[2] = m[2]; dst[3] = m[3];
}

// ============================ kernel 3: load / scan / gather (smem acc) =====
// grid (XG, NQ), 512 threads. Per x: load W column tile (64n x 224y) into
// S[n][y]; hierarchical y-prefix scan; gather: warp walks each batch's
// transition bitmask (warp-uniform), av0/av1 SCALAR register accumulators,
// batch running sums persisted in smem accS[256][64] (NO local memory).
__global__ __launch_bounds__(512, 1)
void main_kernel(const float* __restrict__ W) {
    extern __shared__ float sm[];
    float* S    = sm;                         // [64][PITCH]
    float* accS = sm + OFF_ACC / 4;           // [256][64]
    float* sT   = sm + OFF_TOT / 4;           // [64][4] chunk totals

    const int tid  = threadIdx.x;
    const int w    = tid >> 5;
    const int lane = tid & 31;
    const int xg   = blockIdx.x;
    const int n0   = blockIdx.y * NCOL;

    // zero smem accumulators
#pragma unroll
    for (int r = 0; r < 32; r++) accS[tid + r * 512] = 0.f;
    __syncthreads();

    for (int i = 0; i < XPG; i++) {
        const int x = xg * XPG + i;

        // ---- (a) load: 448 slots (n,seg), 28 per warp, 7-deep batches ----
#pragma unroll
        for (int g = 0; g < 4; g++) {
            float v[7];
            int   nn[7], ss[7];
#pragma unroll
            for (int j = 0; j < 7; j++) {
                int slot = (g * 7 + j) * 16 + w;   // 0..447
                nn[j] = slot / 7;
                ss[j] = slot % 7;
                v[j] = __ldg(&W[(size_t)(n0 + nn[j]) * KTOT +
                                x * IMGC + ss[j] * 32 + lane]);
            }
#pragma unroll
            for (int j = 0; j < 7; j++)
                S[nn[j] * PITCH + ss[j] * 32 + lane] = v[j];
        }
        __syncthreads();

        // ---- (b) scan: 4 threads per column, 56-y chunks + offset fixup ----
        if (tid < 256) {
            const int c = tid >> 2, q = tid & 3;
            float* col = S + c * PITCH + q * 56;
            float run = 0.f;
#pragma unroll
            for (int j = 0; j < 56; j++) { run += col[j]; col[j] = run; }
            sT[c * 4 + q] = run;
        }
        __syncthreads();
        if (tid < 256) {
            const int c = tid >> 2, q = tid & 3;
            if (q > 0) {
                float off = sT[c * 4 + 0];
                if (q > 1) off += sT[c * 4 + 1];
                if (q > 2) off += sT[c * 4 + 2];
                float* col = S + c * PITCH + q * 56;
#pragma unroll
                for (int j = 0; j < 56; j++) col[j] += off;
            }
        }
        __syncthreads();

        // ---- (c) gather: warp w owns batches w*16..w*16+15 ----
        {
            const float* Sl = S + lane * PITCH;         // n = lane
            const float* Sh = S + (lane + 32) * PITCH;  // n = lane+32
#pragma unroll 1
            for (int k = 0; k < 16; k++) {
                const int b = w * 16 + k;
                float av0 = accS[b * NCOL + lane];
                float av1 = accS[b * NCOL + lane + 32];

                const ulonglong2* mp = reinterpret_cast<const ulonglong2*>(
                    g_bits + ((size_t)x * BQ + b) * 4);
                ulonglong2 mA = __ldg(mp), mB = __ldg(mp + 1);
                unsigned long long D0 = mA.x ^ ((mA.x >> 1) | (mA.y << 63));
                unsigned long long D1 = mA.y ^ ((mA.y >> 1) | (mB.x << 63));
                unsigned long long D2 = mB.x ^ ((mB.x >> 1) | (mB.y << 63));
                unsigned long long D3 = mB.y ^ (mB.y >> 1);
                float sgn = (mA.x & 1ull) ? 1.f : -1.f;

                unsigned long long d;
                d = D0;
                while (d) {
                    int p = __ffsll((long long)d) - 1; d &= d - 1;
                    av0 = fmaf(sgn, Sl[p], av0);
                    av1 = fmaf(sgn, Sh[p], av1);
                    sgn = -sgn;
                }
                d = D1;
                while (d) {
                    int p = __ffsll((long long)d) - 1; d &= d - 1;
                    av0 = fmaf(sgn, Sl[64 + p], av0);
                    av1 = fmaf(sgn, Sh[64 + p], av1);
                    sgn = -sgn;
                }
                d = D2;
                while (d) {
                    int p = __ffsll((long long)d) - 1; d &= d - 1;
                    av0 = fmaf(sgn, Sl[128 + p], av0);
                    av1 = fmaf(sgn, Sh[128 + p], av1);
                    sgn = -sgn;
                }
                d = D3;
                while (d) {
                    int p = __ffsll((long long)d) - 1; d &= d - 1;
                    av0 = fmaf(sgn, Sl[192 + p], av0);
                    av1 = fmaf(sgn, Sh[192 + p], av1);
                    sgn = -sgn;
                }

                accS[b * NCOL + lane]      = av0;
                accS[b * NCOL + lane + 32] = av1;
            }
        }
        __syncthreads();
    }

    // ---- write partials: g_part[xg][b][n0+n] ----
#pragma unroll 1
    for (int k = 0; k < 16; k++) {
        const int b = w * 16 + k;
        float* dst = g_part + ((size_t)xg * BQ + b) * OUTN + n0;
        dst[lane]      = accS[b * NCOL + lane];
        dst[lane + 32] = accS[b * NCOL + lane + 32];
    }
}

// ============================ kernel 4: reduce + bias + rgb multiply ========
__global__ void final_kernel(const float* __restrict__ rgb,
                             const float* __restrict__ bias,
                             float* __restrict__ out) {
    const int b = blockIdx.x;
    const int o = threadIdx.x;
    float acc = 0.0f;
    const float* p = g_part + b * OUTN + o;
#pragma unroll
    for (int s = 0; s < XG; s++)
        acc += p[(size_t)s * (BQ * OUTN)];
    out[b * OUTN + o] = rgb[b * OUTN + o] * (acc + bias[o]);
}

// ============================ launch ========================================
extern "C" void kernel_launch(void* const* d_in, const int* in_sizes, int n_in,
                              void* d_out, int out_size) {
    const float* rgb = nullptr;
    const float* sk  = nullptr;
    const float* W   = nullptr;
    const float* bias = nullptr;
    for (int i = 0; i < n_in; i++) {
        switch (in_sizes[i]) {
            case BQ * OUTN:          rgb  = (const float*)d_in[i]; break;
            case BQ * JN * TN * 3:   sk   = (const float*)d_in[i]; break;
            case OUTN * KTOT:        W    = (const float*)d_in[i]; break;
            case OUTN:               bias = (const float*)d_in[i]; break;
            default: break;
        }
    }
    float* out = (float*)d_out;

    cudaFuncSetAttribute(main_kernel,
                         cudaFuncAttributeMaxDynamicSharedMemorySize, SMEM_MAIN);

    prep_kernel<<<(BQ * JN + 255) / 256, 256>>>(sk);
    bitmask_kernel<<<IMGC, BQ>>>();
    main_kernel<<<dim3(XG, NQ), 512, SMEM_MAIN>>>(W);
    final_kernel<<<BQ, OUTN>>>(rgb, bias, out);
}

// round 9
// speedup vs baseline: 1.3512x; 1.3512x over previous
#include <cuda_runtime.h>
#include <cstdint>

// ============================ problem constants ============================
constexpr int IMGC = 224;
constexpr int KTOT = IMGC * IMGC;     // 50176
constexpr int BQ   = 256;
constexpr int JN   = 25;
constexpr int TN   = 64;
constexpr int OUTN = 256;
constexpr int MIDJ = JN / 2;          // 12
constexpr int BOXC = 20;

constexpr int XG   = 56;              // total x groups (2 launches x 28)
constexpr int XPG  = 4;               // x per group: 56*4 = 224
constexpr int NQ   = 4;               // n quarters (grid.y), 64 n each
constexpr uint32_t SMEM_MAIN = 224 * 64 * 4;   // 57344 B: S[224y][64n] swizzled

// ============================ scratch (device globals) =====================
__device__ __align__(256) unsigned long long g_bits[(size_t)IMGC * BQ * 4]; // 1.8MB
__device__ __align__(256) float g_part[(size_t)XG * BQ * OUTN];             // 14.7MB
__device__ int g_px[BQ * JN];
__device__ int g_ylo[BQ * JN];
__device__ int g_yhi[BQ * JN];

// ============================ kernel 1: farthest-frame box params ==========
__global__ void prep_kernel(const float* __restrict__ sk) {
    int id = blockIdx.x * blockDim.x + threadIdx.x;
    if (id >= BQ * JN) return;
    int b = id / JN, j = id % JN;
    const float* base = sk + ((size_t)b * JN + j) * TN * 3;
    const float* midb = sk + ((size_t)b * JN + MIDJ) * TN * 3;

    float best = -1.0f;
    int   tb = 0;
    for (int t = 0; t < TN; t++) {
        float dx = base[t * 3 + 0] - midb[t * 3 + 0];
        float dy = base[t * 3 + 1] - midb[t * 3 + 1];
        float dz = base[t * 3 + 2] - midb[t * 3 + 2];
        float d2 = __fadd_rn(__fadd_rn(__fmul_rn(dx, dx), __fmul_rn(dy, dy)),
                             __fmul_rn(dz, dz));
        float d = __fsqrt_rn(d2);
        if (d > best) { best = d; tb = t; }   // first-max == argmax semantics
    }
    float x = base[tb * 3 + 0];
    float y = base[tb * 3 + 1];
    int px = (int)(__fmul_rn(x, 224.0f));     // truncation == astype(int32)
    int py = (int)(__fmul_rn(y, 224.0f));
    g_px[id]  = px;
    g_ylo[id] = (py < BOXC) ? 0 : py - BOXC;
    g_yhi[id] = (py > IMGC - BOXC) ? IMGC : py + BOXC;
}

// ============================ kernel 2: per-(b,x) y-bitmask =================
__global__ void bitmask_kernel() {
    const int x = blockIdx.x;
    const int b = threadIdx.x;

    unsigned long long m[4] = {0ull, 0ull, 0ull, 0ull};
#pragma unroll
    for (int j = 0; j < JN; j++) {
        if (j == MIDJ) continue;
        int px = g_px[b * JN + j];
        if (x >= px - BOXC && x < px + BOXC) {
            int lo = g_ylo[b * JN + j];
            int hi = g_yhi[b * JN + j];
#pragma unroll
            for (int w = 0; w < 4; w++) {
                int l = lo - w * 64;  if (l < 0)  l = 0;
                int h = hi - w * 64;  if (h > 64) h = 64;
                if (l < h) {
                    unsigned long long hiM = (h == 64) ? ~0ull : ((1ull << h) - 1ull);
                    unsigned long long loM = (1ull << l) - 1ull;
                    m[w] |= hiM & ~loM;
                }
            }
        }
    }
    unsigned long long* dst = g_bits + ((size_t)x * BQ + b) * 4;
    dst[0] = m[0]; dst[1] = m[1]; dst[2] = m[2]; dst[3] = m[3];
}

// ============================ kernel 3: scan + divergent gather (R5 core) ===
// grid (28, NQ), 2 launches (xg_base 0/28). Per x:
//  scan  : warp w scans cols n = 4w..4w+3 (shfl inclusive scan, 7 segments)
//  gather: thread -> (b = tid/2, half), walks transition mask D = m^(m>>1)
//          with alternating sign; 8 float4 LDS per event into static acc[8].
// S layout: float4 slot (n/4 + y) & 15 within row y (rotate swizzle).
__global__ __launch_bounds__(512, 1)
void main_kernel(const float* __restrict__ W, int xg_base) {
    extern __shared__ float sS[];
    const int tid  = threadIdx.x;
    const int w    = tid >> 5;
    const int lane = tid & 31;
    const int xg   = xg_base + blockIdx.x;
    const int n0   = blockIdx.y * 64;
    const int b    = tid >> 1;
    const int half = tid & 1;

    float4 acc[8];
#pragma unroll
    for (int r = 0; r < 8; r++) acc[r] = make_float4(0.f, 0.f, 0.f, 0.f);

    for (int i = 0; i < XPG; i++) {
        const int x = xg * XPG + i;

        // ---- scan: 4 cols per warp, v[4][7] prefetch then shfl scan ----
        {
            const float* wp = W + (size_t)(n0 + w * 4) * KTOT + x * IMGC + lane;
            float v[4][7];
#pragma unroll
            for (int q = 0; q < 4; q++)
#pragma unroll
                for (int s = 0; s < 7; s++)
                    v[q][s] = __ldg(wp + (size_t)q * KTOT + s * 32);

#pragma unroll
            for (int q = 0; q < 4; q++) {
                float carry = 0.f;
#pragma unroll
                for (int s = 0; s < 7; s++) {
                    float val = v[q][s];
#pragma unroll
                    for (int off = 1; off < 32; off <<= 1) {
                        float t = __shfl_up_sync(0xffffffffu, val, off);
                        if (lane >= off) val += t;
                    }
                    val += carry;
                    const int y = s * 32 + lane;
                    sS[y * 64 + (((w + y) & 15) << 2) + q] = val;
                    carry = __shfl_sync(0xffffffffu, val, 31);
                }
            }
        }
        __syncthreads();

        // ---- gather: per-thread divergent walk, alternating sign ----
        {
            const ulonglong2* mp = reinterpret_cast<const ulonglong2*>(
                g_bits + ((size_t)x * BQ + b) * 4);
            ulonglong2 mA = __ldg(mp), mB = __ldg(mp + 1);
            unsigned long long d0 = mA.x ^ ((mA.x >> 1) | (mA.y << 63));
            unsigned long long d1 = mA.y ^ ((mA.y >> 1) | (mB.x << 63));
            unsigned long long d2 = mB.x ^ ((mB.x >> 1) | (mB.y << 63));
            unsigned long long d3 = mB.y ^ (mB.y >> 1);
            float sgn = (mA.x & 1ull) ? 1.f : -1.f;

#pragma unroll
            for (int wd = 0; wd < 4; wd++) {
                unsigned long long d = (wd == 0) ? d0 : (wd == 1) ? d1
                                     : (wd == 2) ? d2 : d3;
                while (d) {
                    int p = __ffsll((long long)d) - 1;
                    d &= d - 1;
                    const int y = wd * 64 + p;
                    const float4* row = reinterpret_cast<const float4*>(sS) + y * 16;
#pragma unroll
                    for (int r = 0; r < 8; r++) {
                        float4 t = row[(half * 8 + r + y) & 15];
                        acc[r].x = fmaf(sgn, t.x, acc[r].x);
                        acc[r].y = fmaf(sgn, t.y, acc[r].y);
                        acc[r].z = fmaf(sgn, t.z, acc[r].z);
                        acc[r].w = fmaf(sgn, t.w, acc[r].w);
                    }
                    sgn = -sgn;
                }
            }
        }
        __syncthreads();
    }

    // ---- write partials ----
    float4* dst = reinterpret_cast<float4*>(
        g_part + ((size_t)xg * BQ + b) * OUTN + n0 + half * 32);
#pragma unroll
    for (int r = 0; r < 8; r++) dst[r] = acc[r];
}

// ============================ kernel 4: reduce + bias + rgb multiply ========
__global__ void final_kernel(const float* __restrict__ rgb,
                             const float* __restrict__ bias,
                             float* __restrict__ out) {
    const int b = blockIdx.x;
    const int o = threadIdx.x;
    float acc = 0.0f;
    const float* p = g_part + b * OUTN + o;
#pragma unroll
    for (int s = 0; s < XG; s++)
        acc += p[(size_t)s * (BQ * OUTN)];
    out[b * OUTN + o] = rgb[b * OUTN + o] * (acc + bias[o]);
}

// ============================ launch ========================================
extern "C" void kernel_launch(void* const* d_in, const int* in_sizes, int n_in,
                              void* d_out, int out_size) {
    const float* rgb = nullptr;
    const float* sk  = nullptr;
    const float* W   = nullptr;
    const float* bias = nullptr;
    for (int i = 0; i < n_in; i++) {
        switch (in_sizes[i]) {
            case BQ * OUTN:          rgb  = (const float*)d_in[i]; break;
            case BQ * JN * TN * 3:   sk   = (const float*)d_in[i]; break;
            case OUTN * KTOT:        W    = (const float*)d_in[i]; break;
            case OUTN:               bias = (const float*)d_in[i]; break;
            default: break;
        }
    }
    float* out = (float*)d_out;

    cudaFuncSetAttribute(main_kernel,
                         cudaFuncAttributeMaxDynamicSharedMemorySize, SMEM_MAIN);

    prep_kernel<<<(BQ * JN + 255) / 256, 256>>>(sk);
    bitmask_kernel<<<IMGC, BQ>>>();
    main_kernel<<<dim3(28, NQ), 512, SMEM_MAIN>>>(W, 0);
    main_kernel<<<dim3(28, NQ), 512, SMEM_MAIN>>>(W, 28);
    final_kernel<<<BQ, OUTN>>>(rgb, bias, out);
}

// round 10
// speedup vs baseline: 1.9348x; 1.4319x over previous
#include <cuda_runtime.h>
#include <cstdint>

// ============================ problem constants ============================
constexpr int IMGC = 224;
constexpr int KTOT = IMGC * IMGC;     // 50176
constexpr int BQ   = 256;
constexpr int JN   = 25;
constexpr int TN   = 64;
constexpr int OUTN = 256;
constexpr int MIDJ = JN / 2;          // 12
constexpr int BOXC = 20;

constexpr int XG   = 37;              // x groups (grid.x) — uneven ranges
constexpr int NO   = 8;               // n octants (grid.y), 32 n each
constexpr int NCOL = 32;              // n per CTA
constexpr uint32_t SMEM_MAIN = 224 * NCOL * 4;   // 28672 B: S[224y][32n] swizzled

// ============================ scratch (device globals) =====================
__device__ __align__(256) unsigned long long g_bits[(size_t)IMGC * BQ * 4]; // 1.8MB
__device__ __align__(256) float g_part[(size_t)XG * BQ * OUTN];             // 9.7MB
__device__ int g_px[BQ * JN];
__device__ int g_ylo[BQ * JN];
__device__ int g_yhi[BQ * JN];

// ============================ kernel 1: farthest-frame box params ==========
__global__ void prep_kernel(const float* __restrict__ sk) {
    int id = blockIdx.x * blockDim.x + threadIdx.x;
    if (id >= BQ * JN) return;
    int b = id / JN, j = id % JN;
    const float* base = sk + ((size_t)b * JN + j) * TN * 3;
    const float* midb = sk + ((size_t)b * JN + MIDJ) * TN * 3;

    float best = -1.0f;
    int   tb = 0;
    for (int t = 0; t < TN; t++) {
        float dx = base[t * 3 + 0] - midb[t * 3 + 0];
        float dy = base[t * 3 + 1] - midb[t * 3 + 1];
        float dz = base[t * 3 + 2] - midb[t * 3 + 2];
        float d2 = __fadd_rn(__fadd_rn(__fmul_rn(dx, dx), __fmul_rn(dy, dy)),
                             __fmul_rn(dz, dz));
        float d = __fsqrt_rn(d2);
        if (d > best) { best = d; tb = t; }   // first-max == argmax semantics
    }
    float x = base[tb * 3 + 0];
    float y = base[tb * 3 + 1];
    int px = (int)(__fmul_rn(x, 224.0f));     // truncation == astype(int32)
    int py = (int)(__fmul_rn(y, 224.0f));
    g_px[id]  = px;
    g_ylo[id] = (py < BOXC) ? 0 : py - BOXC;
    g_yhi[id] = (py > IMGC - BOXC) ? IMGC : py + BOXC;
}

// ============================ kernel 2: per-(b,x) y-bitmask =================
// grid = b (256), threads = x (224); joint params staged through smem.
__global__ void bitmask_kernel() {
    const int b = blockIdx.x;
    const int x = threadIdx.x;

    __shared__ int spx[JN], slo[JN], shi[JN];
    if (x < JN) {
        spx[x] = g_px[b * JN + x];
        slo[x] = g_ylo[b * JN + x];
        shi[x] = g_yhi[b * JN + x];
    }
    __syncthreads();

    unsigned long long m[4] = {0ull, 0ull, 0ull, 0ull};
#pragma unroll
    for (int j = 0; j < JN; j++) {
        if (j == MIDJ) continue;
        int px = spx[j];
        if (x >= px - BOXC && x < px + BOXC) {
            int lo = slo[j], hi = shi[j];
#pragma unroll
            for (int w = 0; w < 4; w++) {
                int l = lo - w * 64;  if (l < 0)  l = 0;
                int h = hi - w * 64;  if (h > 64) h = 64;
                if (l < h) {
                    unsigned long long hiM = (h == 64) ? ~0ull : ((1ull << h) - 1ull);
                    unsigned long long loM = (1ull << l) - 1ull;
                    m[w] |= hiM & ~loM;
                }
            }
        }
    }
    unsigned long long* dst = g_bits + ((size_t)x * BQ + b) * 4;
    dst[0] = m[0]; dst[1] = m[1]; dst[2] = m[2]; dst[3] = m[3];
}

// ============================ kernel 3: scan + divergent gather =============
// grid (37, 8) = 296 CTAs = 2 per SM (the point: CTA A's SHFL-scan overlaps
// CTA B's LDS-gather on the same SM, filling both pipes).
// Per x: scan: warp w scans cols n = 2w, 2w+1 (shfl inclusive, 7 segments);
//        gather: thread (b = tid/2, half), transition mask D = m^(m>>1),
//        alternating sign, 4 float4 LDS per event into static acc[4].
// S layout: 32-float rows; float4 slot of group g=(n>>2) at row y: (g+y)&7.
__global__ __launch_bounds__(512, 2)
void main_kernel(const float* __restrict__ W) {
    extern __shared__ float sS[];
    const int tid  = threadIdx.x;
    const int w    = tid >> 5;
    const int lane = tid & 31;
    const int xg   = blockIdx.x;
    const int n0   = blockIdx.y * NCOL;
    const int b    = tid >> 1;
    const int half = tid & 1;

    const int x0 = (xg * IMGC) / XG;
    const int x1 = ((xg + 1) * IMGC) / XG;

    float4 acc[4];
#pragma unroll
    for (int r = 0; r < 4; r++) acc[r] = make_float4(0.f, 0.f, 0.f, 0.f);

    for (int x = x0; x < x1; x++) {
        // ---- scan: 2 cols per warp, one col at a time (v[7] only) ----
#pragma unroll
        for (int c = 0; c < 2; c++) {
            const int n = w * 2 + c;
            const float* wp = W + (size_t)(n0 + n) * KTOT + x * IMGC + lane;
            float v[7];
#pragma unroll
            for (int s = 0; s < 7; s++) v[s] = __ldg(wp + s * 32);

            float carry = 0.f;
            const int g4 = (n >> 2) & 7;
            const int nc = n & 3;
#pragma unroll
            for (int s = 0; s < 7; s++) {
                float val = v[s];
#pragma unroll
                for (int off = 1; off < 32; off <<= 1) {
                    float t = __shfl_up_sync(0xffffffffu, val, off);
                    if (lane >= off) val += t;
                }
                val += carry;
                const int y = s * 32 + lane;
                sS[y * 32 + (((g4 + y) & 7) << 2) + nc] = val;
                carry = __shfl_sync(0xffffffffu, val, 31);
            }
        }
        __syncthreads();

        // ---- gather: per-thread divergent walk, alternating sign ----
        {
            const ulonglong2* mp = reinterpret_cast<const ulonglong2*>(
                g_bits + ((size_t)x * BQ + b) * 4);
            ulonglong2 mA = __ldg(mp), mB = __ldg(mp + 1);
            unsigned long long d0 = mA.x ^ ((mA.x >> 1) | (mA.y << 63));
            unsigned long long d1 = mA.y ^ ((mA.y >> 1) | (mB.x << 63));
            unsigned long long d2 = mB.x ^ ((mB.x >> 1) | (mB.y << 63));
            unsigned long long d3 = mB.y ^ (mB.y >> 1);
            float sgn = (mA.x & 1ull) ? 1.f : -1.f;

#pragma unroll
            for (int wd = 0; wd < 4; wd++) {
                unsigned long long d = (wd == 0) ? d0 : (wd == 1) ? d1
                                     : (wd == 2) ? d2 : d3;
                while (d) {
                    int p = __ffsll((long long)d) - 1;
                    d &= d - 1;
                    const int y = wd * 64 + p;
                    const float4* row = reinterpret_cast<const float4*>(sS) + y * 8;
#pragma unroll
                    for (int r = 0; r < 4; r++) {
                        float4 t = row[(half * 4 + r + y) & 7];
                        acc[r].x = fmaf(sgn, t.x, acc[r].x);
                        acc[r].y = fmaf(sgn, t.y, acc[r].y);
                        acc[r].z = fmaf(sgn, t.z, acc[r].z);
                        acc[r].w = fmaf(sgn, t.w, acc[r].w);
                    }
                    sgn = -sgn;
                }
            }
        }
        __syncthreads();
    }

    // ---- write partials: acc[r] holds n = n0 + half*16 + 4r .. +3 ----
    float4* dst = reinterpret_cast<float4*>(
        g_part + ((size_t)xg * BQ + b) * OUTN + n0 + half * 16);
#pragma unroll
    for (int r = 0; r < 4; r++) dst[r] = acc[r];
}

// ============================ kernel 4: reduce + bias + rgb multiply ========
__global__ void final_kernel(const float* __restrict__ rgb,
                             const float* __restrict__ bias,
                             float* __restrict__ out) {
    const int b = blockIdx.x;
    const int o = threadIdx.x;
    float acc = 0.0f;
    const float* p = g_part + b * OUTN + o;
#pragma unroll
    for (int s = 0; s < XG; s++)
        acc += p[(size_t)s * (BQ * OUTN)];
    out[b * OUTN + o] = rgb[b * OUTN + o] * (acc + bias[o]);
}

// ============================ launch ========================================
extern "C" void kernel_launch(void* const* d_in, const int* in_sizes, int n_in,
                              void* d_out, int out_size) {
    const float* rgb = nullptr;
    const float* sk  = nullptr;
    const float* W   = nullptr;
    const float* bias = nullptr;
    for (int i = 0; i < n_in; i++) {
        switch (in_sizes[i]) {
            case BQ * OUTN:          rgb  = (const float*)d_in[i]; break;
            case BQ * JN * TN * 3:   sk   = (const float*)d_in[i]; break;
            case OUTN * KTOT:        W    = (const float*)d_in[i]; break;
            case OUTN:               bias = (const float*)d_in[i]; break;
            default: break;
        }
    }
    float* out = (float*)d_out;

    cudaFuncSetAttribute(main_kernel,
                         cudaFuncAttributeMaxDynamicSharedMemorySize, SMEM_MAIN);

    prep_kernel<<<(BQ * JN + 255) / 256, 256>>>(sk);
    bitmask_kernel<<<BQ, IMGC>>>();
    main_kernel<<<dim3(XG, NO), 512, SMEM_MAIN>>>(W);
    final_kernel<<<BQ, OUTN>>>(rgb, bias, out);
}